// round 3
// baseline (speedup 1.0000x reference)
#include <cuda_runtime.h>
#include <math.h>

#define TT 32
#define DD 256
#define HH 768
#define GRIDN 128
#define NT 256

#define OFF_HXLAST (TT*128*HH)
#define OFF_PC     (OFF_HXLAST + 128*HH)
#define OFF_STEPS  (OFF_PC + 128)

typedef unsigned long long ull;

// persistent scratch (allocation-free rule)
__device__ float g_hxi[2][128][HH];      // double-buffered hidden state
__device__ float g_pd[8*128*32];         // per-iteration partial ponder dots [n][row][colgroup]
__device__ unsigned int g_count;         // monotonic grid-barrier counter

struct SM {
  ull   whh[4*192*14];   // W_hh: [j][kq][pair(pad14)] packed col-pairs, 86016 B
  ull   wih[4*64*14];    // W_ih (k<256): same layout, 28672 B
  float base[32][26];    // x@Wih^T + bias, per time step
  float hxn[32][26];     // hx_new tile
  float ahx[32][26];     // accum_hx tile
  float flagw[24];       // W_ih[:,256]
  float wp[24];
  float bias[24];
  float ah[128], sc[128], spc[128], coef[128], pc[128];
  int   mask[128];
};

__device__ __forceinline__ ull fma2(ull a, ull b, ull c){
  ull d; asm("fma.rn.f32x2 %0,%1,%2,%3;" : "=l"(d) : "l"(a), "l"(b), "l"(c)); return d;
}
__device__ __forceinline__ ull add2(ull a, ull b){
  ull d; asm("add.rn.f32x2 %0,%1,%2;" : "=l"(d) : "l"(a), "l"(b)); return d;
}
__device__ __forceinline__ ull dup2(float x){
  ull d; unsigned r = __float_as_uint(x);
  asm("mov.b64 %0,{%1,%1};" : "=l"(d) : "r"(r)); return d;
}
__device__ __forceinline__ ull shx64(ull v, int m){
  unsigned lo = (unsigned)v, hi = (unsigned)(v >> 32);
  lo = __shfl_xor_sync(0xffffffffu, lo, m);
  hi = __shfl_xor_sync(0xffffffffu, hi, m);
  return ((ull)hi << 32) | lo;
}
__device__ __forceinline__ ull bfly(ull v){
  v = add2(v, shx64(v,16)); v = add2(v, shx64(v,8)); v = add2(v, shx64(v,4));
  v = add2(v, shx64(v,2));  v = add2(v, shx64(v,1));
  return v;
}

__device__ __forceinline__ void gbar(){
  __syncthreads();
  if (threadIdx.x == 0){
    __threadfence();
    unsigned prev = atomicAdd(&g_count, 1u);
    unsigned target = prev - (prev & (GRIDN-1u)) + GRIDN;
    unsigned v;
    do { v = *((volatile unsigned*)&g_count); } while ((int)(v - target) < 0);
    __threadfence();
  }
  __syncthreads();
}

// GEMM accumulate: warp tile 8 rows x 12 cols (6 f32x2 pairs), lanes split K.
// k = it*128 + lane*4 + j ; weights at W[((j*KQ + it*32 + lane))*14 + ph*6 ..]
template<int ITK, int KQ, bool CG>
__device__ __forceinline__ void gemm_acc(ull (&acc)[8][6], const float* xbase, int xstride,
                                         const ull* W, int lane, int ph){
  float4 xv[8], xn[8];
  #pragma unroll
  for (int r = 0; r < 8; r++){
    const float4* p = (const float4*)(xbase + r*xstride + lane*4);
    xv[r] = CG ? __ldcg(p) : __ldg(p);
  }
  for (int it = 0; it < ITK; ++it){
    if (it + 1 < ITK){
      #pragma unroll
      for (int r = 0; r < 8; r++){
        const float4* p = (const float4*)(xbase + r*xstride + (it+1)*128 + lane*4);
        xn[r] = CG ? __ldcg(p) : __ldg(p);
      }
    }
    #pragma unroll
    for (int j = 0; j < 4; j++){
      const ulonglong2* w2 = (const ulonglong2*)(W + ((size_t)(j*KQ + it*32 + lane))*14 + ph*6);
      ulonglong2 w0 = w2[0], w1 = w2[1], wq = w2[2];
      #pragma unroll
      for (int r = 0; r < 8; r++){
        ull xd = dup2(((const float*)&xv[r])[j]);
        acc[r][0] = fma2(xd, w0.x, acc[r][0]);
        acc[r][1] = fma2(xd, w0.y, acc[r][1]);
        acc[r][2] = fma2(xd, w1.x, acc[r][2]);
        acc[r][3] = fma2(xd, w1.y, acc[r][3]);
        acc[r][4] = fma2(xd, wq.x, acc[r][4]);
        acc[r][5] = fma2(xd, wq.y, acc[r][5]);
      }
    }
    #pragma unroll
    for (int r = 0; r < 8; r++) xv[r] = xn[r];
  }
}

__global__ void __launch_bounds__(NT, 1)
act_kernel(const float* __restrict__ input, const float* __restrict__ Wih,
           const float* __restrict__ Whh, const float* __restrict__ bih,
           const float* __restrict__ bhh, const float* __restrict__ wpv,
           const float* __restrict__ bpv, float* __restrict__ out)
{
  extern __shared__ unsigned char smraw[];
  SM& s = *reinterpret_cast<SM*>(smraw);
  const int tid = threadIdx.x, blk = blockIdx.x;
  const int rg = blk >> 5, cg = blk & 31;
  const int row0 = rg*32, col0 = cg*24;
  const int lane = tid & 31, warp = tid >> 5;
  const int rsub = warp & 3, ph = warp >> 2;
  const int rbase = rsub*8;

  // ---- one-time: stage weights (transposed, col-pair packed, swizzled) ----
  for (int idx = tid; idx < 24*HH; idx += NT){
    int c = idx / HH, k = idx - c*HH;
    ((float*)&s.whh[((size_t)((k&3)*192 + (k>>2)))*14 + (c>>1)])[c&1] = Whh[(size_t)(col0+c)*HH + k];
  }
  for (int idx = tid; idx < 24*DD; idx += NT){
    int c = idx / DD, k = idx - c*DD;
    ((float*)&s.wih[((size_t)((k&3)*64 + (k>>2)))*14 + (c>>1)])[c&1] = Wih[(size_t)(col0+c)*(DD+1) + k];
  }
  if (tid < 24){
    s.flagw[tid] = Wih[(size_t)(col0+tid)*(DD+1) + DD];
    s.wp[tid]    = wpv[col0+tid];
    s.bias[tid]  = bih[col0+tid] + bhh[col0+tid];
  }
  if (tid < 128) s.pc[tid] = 0.f;
  for (int e = tid; e < 32*24; e += NT){
    int rr = e/24, cc = e - rr*24;
    g_hxi[0][row0+rr][col0+cc] = 0.f;
  }
  const float bp0 = bpv[0];
  int rb = 0;
  gbar();

  for (int t = 0; t < TT; ++t){
    if (tid < 128){ s.ah[tid]=0.f; s.sc[tid]=0.f; s.spc[tid]=0.f; s.mask[tid]=1; }
    for (int e = tid; e < 32*24; e += NT){ int rr=e/24, cc=e-rr*24; s.ahx[rr][cc]=0.f; }

    // ---- per-step: base = x_t @ W_ih^T + b_ih + b_hh (ponder-invariant) ----
    {
      ull acc[8][6];
      #pragma unroll
      for (int r = 0; r < 8; r++){
        #pragma unroll
        for (int p = 0; p < 6; p++) acc[r][p] = 0ull;
      }
      gemm_acc<2,64,false>(acc, input + ((size_t)t*128 + row0 + rbase)*DD, DD, s.wih, lane, ph);
      #pragma unroll
      for (int r = 0; r < 8; r++){
        #pragma unroll
        for (int p = 0; p < 6; p++){
          ull v = bfly(acc[r][p]);
          int i = r*6 + p;
          if (lane == (i & 31)){
            float2 f = *(float2*)&v;
            int rr = rbase + r, cc = ph*12 + p*2;
            s.base[rr][cc]   = f.x + s.bias[cc];
            s.base[rr][cc+1] = f.y + s.bias[cc+1];
          }
        }
      }
    }
    __syncthreads();

    // ---- ponder loop ----
    for (int n = 0; n < 8; ++n){
      ull acc[8][6];
      #pragma unroll
      for (int r = 0; r < 8; r++){
        #pragma unroll
        for (int p = 0; p < 6; p++) acc[r][p] = 0ull;
      }
      gemm_acc<6,192,true>(acc, &g_hxi[rb][row0 + rbase][0], HH, s.whh, lane, ph);

      const float fl = (n == 0) ? 0.f : 1.f;
      #pragma unroll
      for (int r = 0; r < 8; r++){
        #pragma unroll
        for (int p = 0; p < 6; p++){
          ull v = bfly(acc[r][p]);
          int i = r*6 + p;
          if (lane == (i & 31)){
            float2 f = *(float2*)&v;
            int rr = rbase + r, cc = ph*12 + p*2;
            float h0 = tanhf(f.x + s.base[rr][cc]   + fl*s.flagw[cc]);
            float h1 = tanhf(f.y + s.base[rr][cc+1] + fl*s.flagw[cc+1]);
            s.hxn[rr][cc] = h0; s.hxn[rr][cc+1] = h1;
            int gr = row0 + rr, gc = col0 + cc;
            float o0, o1;
            if (s.mask[gr]){ o0 = h0; o1 = h1; }
            else { o0 = __ldcg(&g_hxi[rb][gr][gc]); o1 = __ldcg(&g_hxi[rb][gr][gc+1]); }
            g_hxi[rb^1][gr][gc] = o0; g_hxi[rb^1][gr][gc+1] = o1;
          }
        }
      }
      __syncthreads();
      if (tid < 32){
        float pd = 0.f;
        #pragma unroll
        for (int c = 0; c < 24; c++) pd = fmaf(s.hxn[tid][c], s.wp[c], pd);
        g_pd[(size_t)(n*128 + row0 + tid)*32 + cg] = pd;
      }
      gbar();

      // redundant identical scalar update (fixed summation order => identical on all blocks)
      int nm = 0;
      if (tid < 128){
        const float4* pr = (const float4*)&g_pd[(size_t)(n*128 + tid)*32];
        float sum = 0.f;
        #pragma unroll
        for (int q = 0; q < 8; q++){
          float4 v4 = __ldcg(pr + q);
          sum += v4.x; sum += v4.y; sum += v4.z; sum += v4.w;
        }
        float h = 1.f/(1.f + expf(-(sum + bp0)));
        int   m  = s.mask[tid];
        float mf = m ? 1.f : 0.f;
        if (m) s.spc[tid] = -s.ah[tid];
        float ah2 = s.ah[tid] + mf*h;
        float p2  = h - fmaxf(ah2 - 1.f, 0.f);
        s.coef[tid] = mf*(1.f + p2);
        s.sc[tid]  += mf;
        s.ah[tid]   = ah2;
        int m2 = (ah2 < 0.99f);
        s.mask[tid] = m2;
        nm = m2;
      }
      int nlive = __syncthreads_or(nm);
      for (int e = tid; e < 32*24; e += NT){
        int rr = e/24, cc = e - rr*24;
        s.ahx[rr][cc] = fmaf(s.coef[row0+rr], s.hxn[rr][cc], s.ahx[rr][cc]);
      }
      __syncthreads();
      rb ^= 1;
      if (!nlive) break;
    }

    // ---- end of step: outputs + carry ----
    for (int e = tid; e < 32*24; e += NT){
      int rr = e/24, cc = e - rr*24;
      int gr = row0 + rr, gc = col0 + cc;
      float v = s.ahx[rr][cc] / s.sc[gr];
      out[(size_t)(t*128 + gr)*HH + gc] = v;
      if (t == TT-1) out[OFF_HXLAST + (size_t)gr*HH + gc] = v;
      g_hxi[rb][gr][gc] = v;
    }
    if (blk == 0 && tid < 128){
      s.pc[tid] += s.spc[tid];
      out[OFF_STEPS + t*128 + tid] = s.sc[tid];
    }
    gbar();
  }

  if (blk == 0 && tid < 128) out[OFF_PC + tid] = s.pc[tid];
}

extern "C" void kernel_launch(void* const* d_in, const int* in_sizes, int n_in,
                              void* d_out, int out_size)
{
  const float* input = (const float*)d_in[0];
  const float* Wih   = (const float*)d_in[1];
  const float* Whh   = (const float*)d_in[2];
  const float* bih   = (const float*)d_in[3];
  const float* bhh   = (const float*)d_in[4];
  const float* wpv   = (const float*)d_in[5];
  const float* bpv   = (const float*)d_in[6];
  (void)in_sizes; (void)n_in; (void)out_size;

  cudaFuncSetAttribute(act_kernel, cudaFuncAttributeMaxDynamicSharedMemorySize, (int)sizeof(SM));
  act_kernel<<<GRIDN, NT, sizeof(SM)>>>(input, Wih, Whh, bih, bhh, wpv, bpv, (float*)d_out);
}